// round 11
// baseline (speedup 1.0000x reference)
#include <cuda_runtime.h>
#include <cstdint>

#define L_DIM 2048
#define B_DIM 64
#define D_DEC 1024
#define D_ALIGN 512
#define D_ENC 1024
#define N_SPLIT 8
#define L_PER_SPLIT (L_DIM / N_SPLIT)   // 256
#define GRID_BLOCKS (N_SPLIT * B_DIM)   // 512

// ---- scratch ----
__device__ float g_proj[B_DIM * D_ALIGN];             // 128 KB (final, bias added)
__device__ float g_score[L_DIM * B_DIM];
__device__ float g_m[N_SPLIT * B_DIM];
__device__ float g_partial[N_SPLIT * B_DIM * D_ENC];  // 2 MB
__device__ unsigned g_bar_count;                      // monotonic epoch counter

__device__ __forceinline__ float tanh_approx(float x) {
    float y;
    asm("tanh.approx.f32 %0, %1;" : "=f"(y) : "f"(x));
    return y;
}

__device__ __forceinline__ float4 ldcs4(const float4* p) {
    float4 v;
    asm("ld.global.cs.v4.f32 {%0,%1,%2,%3}, [%4];"
        : "=f"(v.x), "=f"(v.y), "=f"(v.z), "=f"(v.w) : "l"(p));
    return v;
}

// ---- Kernel 1 (merged): proj phase -> device barrier -> fused score/attend ----
// grid (N_SPLIT, B_DIM) = 512 blocks, 256 threads, guaranteed single wave.
__global__ __launch_bounds__(256, 4) void k_main(const float* __restrict__ s_tm1,
                                                 const float* __restrict__ sa_w,
                                                 const float* __restrict__ sa_b,
                                                 const float* __restrict__ uh,
                                                 const float* __restrict__ a1_w,
                                                 const float* __restrict__ a1_b,
                                                 const float* __restrict__ xs_mask,
                                                 const float* __restrict__ xs_h) {
    __shared__ float4 s_stage[D_DEC / 4];     // 4 KB: s_tm1 row for proj phase
    __shared__ float4 s_proj[D_ALIGN / 4];    // 2 KB
    __shared__ float4 s_w[D_ALIGN / 4];       // 2 KB
    __shared__ int   s_list[L_PER_SPLIT];     // 1 KB
    __shared__ float s_sc[L_PER_SPLIT];       // 1 KB
    __shared__ float s_wt[L_PER_SPLIT];       // 1 KB
    __shared__ float red[256];                // 1 KB
    __shared__ int s_wcnt[8];
    __shared__ unsigned s_ball[8];

    int s = blockIdx.x, b = blockIdx.y;
    int tid = threadIdx.x;
    int l0 = s * L_PER_SPLIT;

    // ================= Phase A: proj[b, 64s .. 64s+64) =================
    // Stage s_tm1[b] (256 float4, one per thread)
    s_stage[tid] = ((const float4*)(s_tm1 + (size_t)b * D_DEC))[tid];
    __syncthreads();
    {
        int out = tid >> 2, q = tid & 3;          // quad-per-output
        int a = s * 64 + out;
        const float4* wr = (const float4*)(sa_w + (size_t)a * D_DEC);
        float acc = 0.0f;
#pragma unroll 8
        for (int i = 0; i < 64; i++) {
            int k4 = 4 * i + q;                   // k-interleaved: quad reads 64B contig
            float4 w4 = wr[k4];
            float4 s4 = s_stage[k4];
            acc = fmaf(w4.x, s4.x, acc);
            acc = fmaf(w4.y, s4.y, acc);
            acc = fmaf(w4.z, s4.z, acc);
            acc = fmaf(w4.w, s4.w, acc);
        }
        acc += __shfl_xor_sync(0xFFFFFFFFu, acc, 1);
        acc += __shfl_xor_sync(0xFFFFFFFFu, acc, 2);
        if (q == 0) g_proj[b * D_ALIGN + a] = acc + sa_b[a];
    }

    // ================= Device-wide barrier (epoch counter) =================
    __syncthreads();
    if (tid == 0) {
        __threadfence();
        unsigned t = atomicAdd(&g_bar_count, 1u);
        unsigned target = (t & ~(unsigned)(GRID_BLOCKS - 1)) + GRID_BLOCKS;
        while (*((volatile unsigned*)&g_bar_count) < target) { }
        __threadfence();
    }
    __syncthreads();

    // ================= Phase B: fused score + split softmax + attend ==========
    for (int i = tid; i < D_ALIGN / 4; i += 256) {
        s_proj[i] = ((const float4*)(g_proj + b * D_ALIGN))[i];
        s_w[i] = ((const float4*)a1_w)[i];
    }

    // mask compaction over 256 positions (deterministic ascending)
    {
        int warp8 = tid >> 5, lane = tid & 31;
        float mk = xs_mask[(l0 + tid) * B_DIM + b];
        unsigned ball = __ballot_sync(0xFFFFFFFFu, mk > 0.0f);
        if (lane == 0) {
            s_wcnt[warp8] = __popc(ball);
            s_ball[warp8] = ball;
        }
    }
    __syncthreads();
    int nv = 0;
#pragma unroll
    for (int w = 0; w < 8; w++) nv += s_wcnt[w];
    {
        int warp8 = tid >> 5, lane = tid & 31;
        unsigned ball = s_ball[warp8];
        if ((ball >> lane) & 1u) {
            int off = 0;
#pragma unroll
            for (int w = 0; w < 8; w++) off += (w < warp8) ? s_wcnt[w] : 0;
            int pos = off + __popc(ball & ((1u << lane) - 1u));
            s_list[pos] = tid;
        }
    }
    __syncthreads();

    int warp = tid >> 5, lane = tid & 31;
    float bias = a1_b[0];

    // Phase B1: scores for valid l's only, warp-per-valid-l
    int iters = (nv + 7) >> 3;
    for (int it = 0; it < iters; it++) {
        int j = it * 8 + warp;
        if (j < nv) {
            int l = l0 + s_list[j];
            const float4* row = (const float4*)(uh + ((size_t)(l * B_DIM + b)) * D_ALIGN);
            float sum = 0.0f;
#pragma unroll
            for (int jj = 0; jj < 4; jj++) {
                int a4 = lane + jj * 32;
                float4 u = ldcs4(row + a4);
                float4 p = s_proj[a4];
                float4 w = s_w[a4];
                sum = fmaf(tanh_approx(p.x + u.x), w.x, sum);
                sum = fmaf(tanh_approx(p.y + u.y), w.y, sum);
                sum = fmaf(tanh_approx(p.z + u.z), w.z, sum);
                sum = fmaf(tanh_approx(p.w + u.w), w.w, sum);
            }
#pragma unroll
            for (int o = 16; o > 0; o >>= 1) sum += __shfl_xor_sync(0xFFFFFFFFu, sum, o);
            if (lane == 0) s_sc[j] = sum + bias;
        }
    }
    __syncthreads();

    // split-local max over valid scores (256-wide tree)
    red[tid] = (tid < nv) ? s_sc[tid] : -1e30f;
    __syncthreads();
#pragma unroll
    for (int o = 128; o > 0; o >>= 1) {
        if (tid < o) red[tid] = fmaxf(red[tid], red[tid + o]);
        __syncthreads();
    }
    float m_s = red[0];
    if (tid < nv) {
        float sc = s_sc[tid];
        s_wt[tid] = __expf(sc - m_s);
        g_score[(l0 + s_list[tid]) * B_DIM + b] = sc;
    }
    if (tid == 0) g_m[s * B_DIM + b] = m_s;
    __syncthreads();

    // Phase B2: weighted accumulation over valid xs_h rows, 4-deep batches
    float4 acc = make_float4(0.f, 0.f, 0.f, 0.f);
    const float4* base = (const float4*)xs_h;
    const size_t stride = (size_t)B_DIM * (D_ENC / 4);
    size_t rowbase = ((size_t)(l0 * B_DIM + b)) * (D_ENC / 4) + tid;
    int j = 0;
    for (; j + 3 < nv; j += 4) {
        int i0 = s_list[j], i1 = s_list[j + 1], i2 = s_list[j + 2], i3 = s_list[j + 3];
        float4 v0 = ldcs4(base + rowbase + (size_t)i0 * stride);
        float4 v1 = ldcs4(base + rowbase + (size_t)i1 * stride);
        float4 v2 = ldcs4(base + rowbase + (size_t)i2 * stride);
        float4 v3 = ldcs4(base + rowbase + (size_t)i3 * stride);
        float w0 = s_wt[j], w1 = s_wt[j + 1], w2 = s_wt[j + 2], w3 = s_wt[j + 3];
        acc.x = fmaf(w0, v0.x, acc.x); acc.y = fmaf(w0, v0.y, acc.y);
        acc.z = fmaf(w0, v0.z, acc.z); acc.w = fmaf(w0, v0.w, acc.w);
        acc.x = fmaf(w1, v1.x, acc.x); acc.y = fmaf(w1, v1.y, acc.y);
        acc.z = fmaf(w1, v1.z, acc.z); acc.w = fmaf(w1, v1.w, acc.w);
        acc.x = fmaf(w2, v2.x, acc.x); acc.y = fmaf(w2, v2.y, acc.y);
        acc.z = fmaf(w2, v2.z, acc.z); acc.w = fmaf(w2, v2.w, acc.w);
        acc.x = fmaf(w3, v3.x, acc.x); acc.y = fmaf(w3, v3.y, acc.y);
        acc.z = fmaf(w3, v3.z, acc.z); acc.w = fmaf(w3, v3.w, acc.w);
    }
    for (; j < nv; j++) {
        float4 v = ldcs4(base + rowbase + (size_t)s_list[j] * stride);
        float w = s_wt[j];
        acc.x = fmaf(w, v.x, acc.x); acc.y = fmaf(w, v.y, acc.y);
        acc.z = fmaf(w, v.z, acc.z); acc.w = fmaf(w, v.w, acc.w);
    }
    ((float4*)g_partial)[((s * B_DIM + b) * (D_ENC / 4)) + tid] = acc;
}

// ---- Kernel 2: finalize — global max/Z per b over VALID entries, write
//      e_ij (zeros at masked) and attend ----
__global__ __launch_bounds__(256) void k_finalize(const float* __restrict__ xs_mask,
                                                  float* __restrict__ out) {
    __shared__ float red[256];
    int b = blockIdx.x;
    int tid = threadIdx.x;
    float loc[8], msk[8];
    float m = -1e30f;
#pragma unroll
    for (int i = 0; i < 8; i++) {
        int l = tid + i * 256;
        msk[i] = xs_mask[l * B_DIM + b];
        float sc = g_score[l * B_DIM + b];
        loc[i] = (msk[i] > 0.0f) ? sc : -1e30f;   // never trust masked storage
        m = fmaxf(m, loc[i]);
    }
    red[tid] = m;
    __syncthreads();
#pragma unroll
    for (int o = 128; o > 0; o >>= 1) {
        if (tid < o) red[tid] = fmaxf(red[tid], red[tid + o]);
        __syncthreads();
    }
    m = red[0];
    __syncthreads();
    float e[8];
    float z = 0.0f;
#pragma unroll
    for (int i = 0; i < 8; i++) {
        e[i] = (msk[i] > 0.0f) ? __expf(loc[i] - m) : 0.0f;
        z += e[i];
    }
    red[tid] = z;
    __syncthreads();
#pragma unroll
    for (int o = 128; o > 0; o >>= 1) {
        if (tid < o) red[tid] += red[tid + o];
        __syncthreads();
    }
    float inv = 1.0f / red[0];
#pragma unroll
    for (int i = 0; i < 8; i++) out[(tid + i * 256) * B_DIM + b] = e[i] * inv;

    // attend: rescale split partials by exp(m_s - m) / Z
    float4 acc = make_float4(0.f, 0.f, 0.f, 0.f);
#pragma unroll
    for (int s = 0; s < N_SPLIT; s++) {
        float f = __expf(g_m[s * B_DIM + b] - m);
        float4 v = ((const float4*)g_partial)[((s * B_DIM + b) * (D_ENC / 4)) + tid];
        acc.x = fmaf(f, v.x, acc.x);
        acc.y = fmaf(f, v.y, acc.y);
        acc.z = fmaf(f, v.z, acc.z);
        acc.w = fmaf(f, v.w, acc.w);
    }
    acc.x *= inv; acc.y *= inv; acc.z *= inv; acc.w *= inv;
    ((float4*)(out + L_DIM * B_DIM))[b * (D_ENC / 4) + tid] = acc;
}

extern "C" void kernel_launch(void* const* d_in, const int* in_sizes, int n_in,
                              void* d_out, int out_size) {
    const float* s_tm1   = (const float*)d_in[0];
    const float* xs_h    = (const float*)d_in[1];
    const float* uh      = (const float*)d_in[2];
    const float* xs_mask = (const float*)d_in[3];
    const float* sa_w    = (const float*)d_in[4];
    const float* sa_b    = (const float*)d_in[5];
    const float* a1_w    = (const float*)d_in[6];
    const float* a1_b    = (const float*)d_in[7];
    float* out = (float*)d_out;

    dim3 g1(N_SPLIT, B_DIM);
    k_main<<<g1, 256>>>(s_tm1, sa_w, sa_b, uh, a1_w, a1_b, xs_mask, xs_h);
    k_finalize<<<B_DIM, 256>>>(xs_mask, out);
}

// round 12
// speedup vs baseline: 1.0482x; 1.0482x over previous
#include <cuda_runtime.h>
#include <cstdint>

#define L_DIM 2048
#define B_DIM 64
#define D_DEC 1024
#define D_ALIGN 512
#define D_ENC 1024
#define N_SPLIT 16
#define L_PER_SPLIT (L_DIM / N_SPLIT)   // 128
#define K_SPLIT 4
#define K_CHUNK (D_DEC / K_SPLIT)       // 256

// ---- scratch ----
__device__ float g_proj_part[K_SPLIT][B_DIM * D_ALIGN];  // 512 KB
__device__ float g_score[L_DIM * B_DIM];
__device__ float g_m[N_SPLIT * B_DIM];
__device__ float g_partial[N_SPLIT * B_DIM * D_ENC];     // 4 MB
__device__ float2 g_stats[B_DIM];                        // {m_global, 1/Z}

__device__ __forceinline__ float tanh_approx(float x) {
    float y;
    asm("tanh.approx.f32 %0, %1;" : "=f"(y) : "f"(x));
    return y;
}

__device__ __forceinline__ float4 ldcs4(const float4* p) {
    float4 v;
    asm("ld.global.cs.v4.f32 {%0,%1,%2,%3}, [%4];"
        : "=f"(v.x), "=f"(v.y), "=f"(v.z), "=f"(v.w) : "l"(p));
    return v;
}

// ---- Kernel 1: split-K partial proj, thread-per-output (R9 shape) ----
__global__ __launch_bounds__(256) void k_projp(const float* __restrict__ s_tm1,
                                               const float* __restrict__ sa_w) {
    __shared__ float4 sw[32][(K_CHUNK / 4) + 1];
    __shared__ float4 ss[8][(K_CHUNK / 4) + 1];
    int a0 = blockIdx.x * 32, b0 = blockIdx.y * 8;
    int k0 = blockIdx.z * K_CHUNK;
    for (int i = threadIdx.x; i < 32 * (K_CHUNK / 4); i += 256) {
        int r = i >> 6, c = i & 63;
        sw[r][c] = ((const float4*)(sa_w + (size_t)(a0 + r) * D_DEC + k0))[c];
    }
    for (int i = threadIdx.x; i < 8 * (K_CHUNK / 4); i += 256) {
        int r = i >> 6, c = i & 63;
        ss[r][c] = ((const float4*)(s_tm1 + (size_t)(b0 + r) * D_DEC + k0))[c];
    }
    __syncthreads();
    int al = threadIdx.x >> 3, bl = threadIdx.x & 7;
    float acc0 = 0.f, acc1 = 0.f;
#pragma unroll 8
    for (int j = 0; j < K_CHUNK / 4; j += 2) {
        float4 w0 = sw[al][j];
        float4 s0 = ss[bl][j];
        float4 w1 = sw[al][j + 1];
        float4 s1 = ss[bl][j + 1];
        acc0 = fmaf(w0.x, s0.x, acc0);
        acc0 = fmaf(w0.y, s0.y, acc0);
        acc0 = fmaf(w0.z, s0.z, acc0);
        acc0 = fmaf(w0.w, s0.w, acc0);
        acc1 = fmaf(w1.x, s1.x, acc1);
        acc1 = fmaf(w1.y, s1.y, acc1);
        acc1 = fmaf(w1.z, s1.z, acc1);
        acc1 = fmaf(w1.w, s1.w, acc1);
    }
    g_proj_part[blockIdx.z][(b0 + bl) * D_ALIGN + a0 + al] = acc0 + acc1;
}

// ---- Kernel 2 (fused, mask-skipping): unchanged from R9 ----
__global__ __launch_bounds__(256) void k_fused(const float* __restrict__ uh,
                                               const float* __restrict__ sa_b,
                                               const float* __restrict__ a1_w,
                                               const float* __restrict__ a1_b,
                                               const float* __restrict__ xs_mask,
                                               const float* __restrict__ xs_h) {
    __shared__ float4 s_proj[D_ALIGN / 4];
    __shared__ float4 s_w[D_ALIGN / 4];
    __shared__ int   s_list[L_PER_SPLIT];
    __shared__ float s_sc[L_PER_SPLIT];
    __shared__ float s_wt[L_PER_SPLIT];
    __shared__ float red[128];
    __shared__ int s_wcnt[4];
    __shared__ unsigned s_ball[4];
    int s = blockIdx.x, b = blockIdx.y;
    int tid = threadIdx.x;
    int l0 = s * L_PER_SPLIT;

    for (int i = tid; i < D_ALIGN / 4; i += 256) {
        float4 p0 = ((const float4*)(g_proj_part[0] + b * D_ALIGN))[i];
        float4 p1 = ((const float4*)(g_proj_part[1] + b * D_ALIGN))[i];
        float4 p2 = ((const float4*)(g_proj_part[2] + b * D_ALIGN))[i];
        float4 p3 = ((const float4*)(g_proj_part[3] + b * D_ALIGN))[i];
        float4 sb = ((const float4*)sa_b)[i];
        s_proj[i] = make_float4((((p0.x + p1.x) + p2.x) + p3.x) + sb.x,
                                (((p0.y + p1.y) + p2.y) + p3.y) + sb.y,
                                (((p0.z + p1.z) + p2.z) + p3.z) + sb.z,
                                (((p0.w + p1.w) + p2.w) + p3.w) + sb.w);
        s_w[i] = ((const float4*)a1_w)[i];
    }

    // mask compaction (deterministic ascending)
    if (tid < 128) {
        int warp4 = tid >> 5, lane = tid & 31;
        float mk = xs_mask[(l0 + tid) * B_DIM + b];
        unsigned ball = __ballot_sync(0xFFFFFFFFu, mk > 0.0f);
        if (lane == 0) {
            s_wcnt[warp4] = __popc(ball);
            s_ball[warp4] = ball;
        }
    }
    __syncthreads();
    int nv = s_wcnt[0] + s_wcnt[1] + s_wcnt[2] + s_wcnt[3];
    if (tid < 128) {
        int warp4 = tid >> 5, lane = tid & 31;
        unsigned ball = s_ball[warp4];
        if ((ball >> lane) & 1u) {
            int off = 0;
#pragma unroll
            for (int w = 0; w < 4; w++) off += (w < warp4) ? s_wcnt[w] : 0;
            int pos = off + __popc(ball & ((1u << lane) - 1u));
            s_list[pos] = tid;
        }
    }
    __syncthreads();

    int warp = tid >> 5, lane = tid & 31;
    float bias = a1_b[0];

    int iters = (nv + 7) >> 3;
    for (int it = 0; it < iters; it++) {
        int j = it * 8 + warp;
        if (j < nv) {
            int l = l0 + s_list[j];
            const float4* row = (const float4*)(uh + ((size_t)(l * B_DIM + b)) * D_ALIGN);
            float sum = 0.0f;
#pragma unroll
            for (int jj = 0; jj < 4; jj++) {
                int a4 = lane + jj * 32;
                float4 u = ldcs4(row + a4);
                float4 p = s_proj[a4];
                float4 w = s_w[a4];
                sum = fmaf(tanh_approx(p.x + u.x), w.x, sum);
                sum = fmaf(tanh_approx(p.y + u.y), w.y, sum);
                sum = fmaf(tanh_approx(p.z + u.z), w.z, sum);
                sum = fmaf(tanh_approx(p.w + u.w), w.w, sum);
            }
#pragma unroll
            for (int o = 16; o > 0; o >>= 1) sum += __shfl_xor_sync(0xFFFFFFFFu, sum, o);
            if (lane == 0) s_sc[j] = sum + bias;
        }
    }
    __syncthreads();

    if (tid < 128) red[tid] = (tid < nv) ? s_sc[tid] : -1e30f;
    __syncthreads();
#pragma unroll
    for (int o = 64; o > 0; o >>= 1) {
        if (tid < o) red[tid] = fmaxf(red[tid], red[tid + o]);
        __syncthreads();
    }
    float m_s = red[0];
    if (tid < nv) {
        float sc = s_sc[tid];
        s_wt[tid] = __expf(sc - m_s);
        g_score[(l0 + s_list[tid]) * B_DIM + b] = sc;
    }
    if (tid == 0) g_m[s * B_DIM + b] = m_s;
    __syncthreads();

    float4 acc = make_float4(0.f, 0.f, 0.f, 0.f);
    const float4* base = (const float4*)xs_h;
    const size_t stride = (size_t)B_DIM * (D_ENC / 4);
    size_t rowbase = ((size_t)(l0 * B_DIM + b)) * (D_ENC / 4) + tid;
    int j = 0;
    for (; j + 3 < nv; j += 4) {
        int i0 = s_list[j], i1 = s_list[j + 1], i2 = s_list[j + 2], i3 = s_list[j + 3];
        float4 v0 = ldcs4(base + rowbase + (size_t)i0 * stride);
        float4 v1 = ldcs4(base + rowbase + (size_t)i1 * stride);
        float4 v2 = ldcs4(base + rowbase + (size_t)i2 * stride);
        float4 v3 = ldcs4(base + rowbase + (size_t)i3 * stride);
        float w0 = s_wt[j], w1 = s_wt[j + 1], w2 = s_wt[j + 2], w3 = s_wt[j + 3];
        acc.x = fmaf(w0, v0.x, acc.x); acc.y = fmaf(w0, v0.y, acc.y);
        acc.z = fmaf(w0, v0.z, acc.z); acc.w = fmaf(w0, v0.w, acc.w);
        acc.x = fmaf(w1, v1.x, acc.x); acc.y = fmaf(w1, v1.y, acc.y);
        acc.z = fmaf(w1, v1.z, acc.z); acc.w = fmaf(w1, v1.w, acc.w);
        acc.x = fmaf(w2, v2.x, acc.x); acc.y = fmaf(w2, v2.y, acc.y);
        acc.z = fmaf(w2, v2.z, acc.z); acc.w = fmaf(w2, v2.w, acc.w);
        acc.x = fmaf(w3, v3.x, acc.x); acc.y = fmaf(w3, v3.y, acc.y);
        acc.z = fmaf(w3, v3.z, acc.z); acc.w = fmaf(w3, v3.w, acc.w);
    }
    for (; j < nv; j++) {
        float4 v = ldcs4(base + rowbase + (size_t)s_list[j] * stride);
        float w = s_wt[j];
        acc.x = fmaf(w, v.x, acc.x); acc.y = fmaf(w, v.y, acc.y);
        acc.z = fmaf(w, v.z, acc.z); acc.w = fmaf(w, v.w, acc.w);
    }
    ((float4*)g_partial)[((s * B_DIM + b) * (D_ENC / 4)) + tid] = acc;
}

// ---- Kernel 3a: per-b softmax stats (m, 1/Z) ----
__global__ __launch_bounds__(256) void k_stats(const float* __restrict__ xs_mask) {
    __shared__ float red[256];
    int b = blockIdx.x;
    int tid = threadIdx.x;
    float loc[8], msk[8];
    float m = -1e30f;
#pragma unroll
    for (int i = 0; i < 8; i++) {
        int l = tid + i * 256;
        msk[i] = xs_mask[l * B_DIM + b];
        float sc = g_score[l * B_DIM + b];
        loc[i] = (msk[i] > 0.0f) ? sc : -1e30f;
        m = fmaxf(m, loc[i]);
    }
    red[tid] = m;
    __syncthreads();
#pragma unroll
    for (int o = 128; o > 0; o >>= 1) {
        if (tid < o) red[tid] = fmaxf(red[tid], red[tid + o]);
        __syncthreads();
    }
    m = red[0];
    __syncthreads();
    float z = 0.0f;
#pragma unroll
    for (int i = 0; i < 8; i++)
        z += (msk[i] > 0.0f) ? __expf(loc[i] - m) : 0.0f;
    red[tid] = z;
    __syncthreads();
#pragma unroll
    for (int o = 128; o > 0; o >>= 1) {
        if (tid < o) red[tid] += red[tid + o];
        __syncthreads();
    }
    if (tid == 0) g_stats[b] = make_float2(m, 1.0f / red[0]);
}

// ---- Kernel 3b: wide write — e_ij columns (t<8) and attend (t==8) ----
__global__ __launch_bounds__(256) void k_write(const float* __restrict__ xs_mask,
                                               float* __restrict__ out) {
    int t = blockIdx.x, b = blockIdx.y;
    int tid = threadIdx.x;
    float2 st = g_stats[b];
    float m = st.x, inv = st.y;
    if (t < 8) {
        int l = t * 256 + tid;
        float msk = xs_mask[l * B_DIM + b];
        float e = 0.0f;
        if (msk > 0.0f) e = __expf(g_score[l * B_DIM + b] - m) * inv;
        out[l * B_DIM + b] = e;
    } else {
        // attend: thread tid -> float4 tid of row b; rescale split partials
        float4 acc = make_float4(0.f, 0.f, 0.f, 0.f);
#pragma unroll
        for (int s = 0; s < N_SPLIT; s++) {
            float f = __expf(g_m[s * B_DIM + b] - m);
            float4 v = ((const float4*)g_partial)[((s * B_DIM + b) * (D_ENC / 4)) + tid];
            acc.x = fmaf(f, v.x, acc.x);
            acc.y = fmaf(f, v.y, acc.y);
            acc.z = fmaf(f, v.z, acc.z);
            acc.w = fmaf(f, v.w, acc.w);
        }
        acc.x *= inv; acc.y *= inv; acc.z *= inv; acc.w *= inv;
        ((float4*)(out + L_DIM * B_DIM))[b * (D_ENC / 4) + tid] = acc;
    }
}

extern "C" void kernel_launch(void* const* d_in, const int* in_sizes, int n_in,
                              void* d_out, int out_size) {
    const float* s_tm1   = (const float*)d_in[0];
    const float* xs_h    = (const float*)d_in[1];
    const float* uh      = (const float*)d_in[2];
    const float* xs_mask = (const float*)d_in[3];
    const float* sa_w    = (const float*)d_in[4];
    const float* sa_b    = (const float*)d_in[5];
    const float* a1_w    = (const float*)d_in[6];
    const float* a1_b    = (const float*)d_in[7];
    float* out = (float*)d_out;

    dim3 g1(16, 8, K_SPLIT);
    k_projp<<<g1, 256>>>(s_tm1, sa_w);
    dim3 g2(N_SPLIT, B_DIM);
    k_fused<<<g2, 256>>>(uh, sa_b, a1_w, a1_b, xs_mask, xs_h);
    k_stats<<<B_DIM, 256>>>(xs_mask);
    dim3 g4(9, B_DIM);
    k_write<<<g4, 256>>>(xs_mask, out);
}

// round 13
// speedup vs baseline: 1.0664x; 1.0174x over previous
#include <cuda_runtime.h>
#include <cstdint>

#define L_DIM 2048
#define B_DIM 64
#define D_DEC 1024
#define D_ALIGN 512
#define D_ENC 1024
#define N_SPLIT 16
#define L_PER_SPLIT (L_DIM / N_SPLIT)   // 128
#define K_SPLIT 4
#define K_CHUNK (D_DEC / K_SPLIT)       // 256

// ---- scratch ----
__device__ float g_proj_part[K_SPLIT][B_DIM * D_ALIGN];  // 512 KB
__device__ float g_score[L_DIM * B_DIM];
__device__ float g_m[N_SPLIT * B_DIM];
__device__ float g_z[N_SPLIT * B_DIM];
__device__ float g_partial[N_SPLIT * B_DIM * D_ENC];     // 4 MB
__device__ float2 g_stats[B_DIM];                        // {m_global, 1/Z}

__device__ __forceinline__ float tanh_approx(float x) {
    float y;
    asm("tanh.approx.f32 %0, %1;" : "=f"(y) : "f"(x));
    return y;
}

__device__ __forceinline__ float4 ldcs4(const float4* p) {
    float4 v;
    asm("ld.global.cs.v4.f32 {%0,%1,%2,%3}, [%4];"
        : "=f"(v.x), "=f"(v.y), "=f"(v.z), "=f"(v.w) : "l"(p));
    return v;
}

// ---- Kernel 1: split-K partial proj, thread-per-output (R9 shape) ----
__global__ __launch_bounds__(256) void k_projp(const float* __restrict__ s_tm1,
                                               const float* __restrict__ sa_w) {
    __shared__ float4 sw[32][(K_CHUNK / 4) + 1];
    __shared__ float4 ss[8][(K_CHUNK / 4) + 1];
    int a0 = blockIdx.x * 32, b0 = blockIdx.y * 8;
    int k0 = blockIdx.z * K_CHUNK;
    for (int i = threadIdx.x; i < 32 * (K_CHUNK / 4); i += 256) {
        int r = i >> 6, c = i & 63;
        sw[r][c] = ((const float4*)(sa_w + (size_t)(a0 + r) * D_DEC + k0))[c];
    }
    for (int i = threadIdx.x; i < 8 * (K_CHUNK / 4); i += 256) {
        int r = i >> 6, c = i & 63;
        ss[r][c] = ((const float4*)(s_tm1 + (size_t)(b0 + r) * D_DEC + k0))[c];
    }
    __syncthreads();
    int al = threadIdx.x >> 3, bl = threadIdx.x & 7;
    float acc0 = 0.f, acc1 = 0.f;
#pragma unroll 8
    for (int j = 0; j < K_CHUNK / 4; j += 2) {
        float4 w0 = sw[al][j];
        float4 s0 = ss[bl][j];
        float4 w1 = sw[al][j + 1];
        float4 s1 = ss[bl][j + 1];
        acc0 = fmaf(w0.x, s0.x, acc0);
        acc0 = fmaf(w0.y, s0.y, acc0);
        acc0 = fmaf(w0.z, s0.z, acc0);
        acc0 = fmaf(w0.w, s0.w, acc0);
        acc1 = fmaf(w1.x, s1.x, acc1);
        acc1 = fmaf(w1.y, s1.y, acc1);
        acc1 = fmaf(w1.z, s1.z, acc1);
        acc1 = fmaf(w1.w, s1.w, acc1);
    }
    g_proj_part[blockIdx.z][(b0 + bl) * D_ALIGN + a0 + al] = acc0 + acc1;
}

// ---- Kernel 2 (fused, mask-skipping + split Z reduction) ----
__global__ __launch_bounds__(256) void k_fused(const float* __restrict__ uh,
                                               const float* __restrict__ sa_b,
                                               const float* __restrict__ a1_w,
                                               const float* __restrict__ a1_b,
                                               const float* __restrict__ xs_mask,
                                               const float* __restrict__ xs_h) {
    __shared__ float4 s_proj[D_ALIGN / 4];
    __shared__ float4 s_w[D_ALIGN / 4];
    __shared__ int   s_list[L_PER_SPLIT];
    __shared__ float s_sc[L_PER_SPLIT];
    __shared__ float s_wt[L_PER_SPLIT];
    __shared__ float red[128];
    __shared__ int s_wcnt[4];
    __shared__ unsigned s_ball[4];
    int s = blockIdx.x, b = blockIdx.y;
    int tid = threadIdx.x;
    int l0 = s * L_PER_SPLIT;

    for (int i = tid; i < D_ALIGN / 4; i += 256) {
        float4 p0 = ((const float4*)(g_proj_part[0] + b * D_ALIGN))[i];
        float4 p1 = ((const float4*)(g_proj_part[1] + b * D_ALIGN))[i];
        float4 p2 = ((const float4*)(g_proj_part[2] + b * D_ALIGN))[i];
        float4 p3 = ((const float4*)(g_proj_part[3] + b * D_ALIGN))[i];
        float4 sb = ((const float4*)sa_b)[i];
        s_proj[i] = make_float4((((p0.x + p1.x) + p2.x) + p3.x) + sb.x,
                                (((p0.y + p1.y) + p2.y) + p3.y) + sb.y,
                                (((p0.z + p1.z) + p2.z) + p3.z) + sb.z,
                                (((p0.w + p1.w) + p2.w) + p3.w) + sb.w);
        s_w[i] = ((const float4*)a1_w)[i];
    }

    // mask compaction (deterministic ascending)
    if (tid < 128) {
        int warp4 = tid >> 5, lane = tid & 31;
        float mk = xs_mask[(l0 + tid) * B_DIM + b];
        unsigned ball = __ballot_sync(0xFFFFFFFFu, mk > 0.0f);
        if (lane == 0) {
            s_wcnt[warp4] = __popc(ball);
            s_ball[warp4] = ball;
        }
    }
    __syncthreads();
    int nv = s_wcnt[0] + s_wcnt[1] + s_wcnt[2] + s_wcnt[3];
    if (tid < 128) {
        int warp4 = tid >> 5, lane = tid & 31;
        unsigned ball = s_ball[warp4];
        if ((ball >> lane) & 1u) {
            int off = 0;
#pragma unroll
            for (int w = 0; w < 4; w++) off += (w < warp4) ? s_wcnt[w] : 0;
            int pos = off + __popc(ball & ((1u << lane) - 1u));
            s_list[pos] = tid;
        }
    }
    __syncthreads();

    int warp = tid >> 5, lane = tid & 31;
    float bias = a1_b[0];

    int iters = (nv + 7) >> 3;
    for (int it = 0; it < iters; it++) {
        int j = it * 8 + warp;
        if (j < nv) {
            int l = l0 + s_list[j];
            const float4* row = (const float4*)(uh + ((size_t)(l * B_DIM + b)) * D_ALIGN);
            float sum = 0.0f;
#pragma unroll
            for (int jj = 0; jj < 4; jj++) {
                int a4 = lane + jj * 32;
                float4 u = ldcs4(row + a4);
                float4 p = s_proj[a4];
                float4 w = s_w[a4];
                sum = fmaf(tanh_approx(p.x + u.x), w.x, sum);
                sum = fmaf(tanh_approx(p.y + u.y), w.y, sum);
                sum = fmaf(tanh_approx(p.z + u.z), w.z, sum);
                sum = fmaf(tanh_approx(p.w + u.w), w.w, sum);
            }
#pragma unroll
            for (int o = 16; o > 0; o >>= 1) sum += __shfl_xor_sync(0xFFFFFFFFu, sum, o);
            if (lane == 0) s_sc[j] = sum + bias;
        }
    }
    __syncthreads();

    // split-local max
    if (tid < 128) red[tid] = (tid < nv) ? s_sc[tid] : -1e30f;
    __syncthreads();
#pragma unroll
    for (int o = 64; o > 0; o >>= 1) {
        if (tid < o) red[tid] = fmaxf(red[tid], red[tid + o]);
        __syncthreads();
    }
    float m_s = red[0];
    __syncthreads();
    if (tid < nv) {
        float sc = s_sc[tid];
        s_wt[tid] = __expf(sc - m_s);
        g_score[(l0 + s_list[tid]) * B_DIM + b] = sc;
    }
    // split-local Z = sum of exp weights
    if (tid < 128) red[tid] = (tid < nv) ? __expf(s_sc[tid] - m_s) : 0.0f;
    __syncthreads();
#pragma unroll
    for (int o = 64; o > 0; o >>= 1) {
        if (tid < o) red[tid] += red[tid + o];
        __syncthreads();
    }
    if (tid == 0) {
        g_m[s * B_DIM + b] = m_s;
        g_z[s * B_DIM + b] = red[0];
    }
    __syncthreads();

    float4 acc = make_float4(0.f, 0.f, 0.f, 0.f);
    const float4* base = (const float4*)xs_h;
    const size_t stride = (size_t)B_DIM * (D_ENC / 4);
    size_t rowbase = ((size_t)(l0 * B_DIM + b)) * (D_ENC / 4) + tid;
    int j = 0;
    for (; j + 3 < nv; j += 4) {
        int i0 = s_list[j], i1 = s_list[j + 1], i2 = s_list[j + 2], i3 = s_list[j + 3];
        float4 v0 = ldcs4(base + rowbase + (size_t)i0 * stride);
        float4 v1 = ldcs4(base + rowbase + (size_t)i1 * stride);
        float4 v2 = ldcs4(base + rowbase + (size_t)i2 * stride);
        float4 v3 = ldcs4(base + rowbase + (size_t)i3 * stride);
        float w0 = s_wt[j], w1 = s_wt[j + 1], w2 = s_wt[j + 2], w3 = s_wt[j + 3];
        acc.x = fmaf(w0, v0.x, acc.x); acc.y = fmaf(w0, v0.y, acc.y);
        acc.z = fmaf(w0, v0.z, acc.z); acc.w = fmaf(w0, v0.w, acc.w);
        acc.x = fmaf(w1, v1.x, acc.x); acc.y = fmaf(w1, v1.y, acc.y);
        acc.z = fmaf(w1, v1.z, acc.z); acc.w = fmaf(w1, v1.w, acc.w);
        acc.x = fmaf(w2, v2.x, acc.x); acc.y = fmaf(w2, v2.y, acc.y);
        acc.z = fmaf(w2, v2.z, acc.z); acc.w = fmaf(w2, v2.w, acc.w);
        acc.x = fmaf(w3, v3.x, acc.x); acc.y = fmaf(w3, v3.y, acc.y);
        acc.z = fmaf(w3, v3.z, acc.z); acc.w = fmaf(w3, v3.w, acc.w);
    }
    for (; j < nv; j++) {
        float4 v = ldcs4(base + rowbase + (size_t)s_list[j] * stride);
        float w = s_wt[j];
        acc.x = fmaf(w, v.x, acc.x); acc.y = fmaf(w, v.y, acc.y);
        acc.z = fmaf(w, v.z, acc.z); acc.w = fmaf(w, v.w, acc.w);
    }
    ((float4*)g_partial)[((s * B_DIM + b) * (D_ENC / 4)) + tid] = acc;
}

// ---- Kernel 3a: tiny per-b stats combine from split (m_s, z_s) ----
__global__ __launch_bounds__(64) void k_stats() {
    int b = threadIdx.x;   // 0..63, single block
    float m = -1e30f;
#pragma unroll
    for (int s = 0; s < N_SPLIT; s++) m = fmaxf(m, g_m[s * B_DIM + b]);
    float z = 0.0f;
#pragma unroll
    for (int s = 0; s < N_SPLIT; s++)
        z += g_z[s * B_DIM + b] * __expf(g_m[s * B_DIM + b] - m);
    g_stats[b] = make_float2(m, 1.0f / z);
}

// ---- Kernel 3b: coalesced write — e_ij (linear blocks) and attend ----
__global__ __launch_bounds__(256) void k_write(const float* __restrict__ xs_mask,
                                               float* __restrict__ out) {
    int t = blockIdx.x;
    int tid = threadIdx.x;
    if (t < (L_DIM * B_DIM) / 256) {
        // coalesced: idx runs linearly over [L, B]
        int idx = t * 256 + tid;
        int b = idx & (B_DIM - 1);
        float2 st = g_stats[b];
        float msk = xs_mask[idx];
        float e = 0.0f;
        if (msk > 0.0f) e = __expf(g_score[idx] - st.x) * st.y;
        out[idx] = e;
    } else {
        // attend: block per b; thread tid -> float4 col; rescale split partials
        int b = t - (L_DIM * B_DIM) / 256;
        float2 st = g_stats[b];
        float m = st.x, inv = st.y;
        float4 acc = make_float4(0.f, 0.f, 0.f, 0.f);
#pragma unroll
        for (int s = 0; s < N_SPLIT; s++) {
            float f = __expf(g_m[s * B_DIM + b] - m);
            float4 v = ((const float4*)g_partial)[((s * B_DIM + b) * (D_ENC / 4)) + tid];
            acc.x = fmaf(f, v.x, acc.x);
            acc.y = fmaf(f, v.y, acc.y);
            acc.z = fmaf(f, v.z, acc.z);
            acc.w = fmaf(f, v.w, acc.w);
        }
        acc.x *= inv; acc.y *= inv; acc.z *= inv; acc.w *= inv;
        ((float4*)(out + L_DIM * B_DIM))[b * (D_ENC / 4) + tid] = acc;
    }
}

extern "C" void kernel_launch(void* const* d_in, const int* in_sizes, int n_in,
                              void* d_out, int out_size) {
    const float* s_tm1   = (const float*)d_in[0];
    const float* xs_h    = (const float*)d_in[1];
    const float* uh      = (const float*)d_in[2];
    const float* xs_mask = (const float*)d_in[3];
    const float* sa_w    = (const float*)d_in[4];
    const float* sa_b    = (const float*)d_in[5];
    const float* a1_w    = (const float*)d_in[6];
    const float* a1_b    = (const float*)d_in[7];
    float* out = (float*)d_out;

    dim3 g1(16, 8, K_SPLIT);
    k_projp<<<g1, 256>>>(s_tm1, sa_w);
    dim3 g2(N_SPLIT, B_DIM);
    k_fused<<<g2, 256>>>(uh, sa_b, a1_w, a1_b, xs_mask, xs_h);
    k_stats<<<1, 64>>>();
    k_write<<<(L_DIM * B_DIM) / 256 + B_DIM, 256>>>(xs_mask, out);
}